// round 3
// baseline (speedup 1.0000x reference)
#include <cuda_runtime.h>
#include <cstdint>
#include <cstddef>

#define B_  64
#define S_  512
#define E_  1024
#define H_  1024
#define NG  4096            // 4 gates * H
#define NCTA 128

typedef unsigned long long ull;

// ---------------- device scratch (static: no allocations allowed) ----------
__device__ float g_xg[(size_t)S_ * B_ * NG];   // [t][b][n]  512 MB
__device__ float g_h[2][B_ * H_];              // double-buffered hidden state [b][k]
__device__ unsigned g_bar_count = 0;
__device__ unsigned g_bar_gen   = 0;

// ---------------- packed fp32x2 helpers (full-rate fp32 on sm_103a) --------
__device__ __forceinline__ void fma2(ull& d, ull a, ull b) {
    asm("fma.rn.f32x2 %0, %1, %2, %0;" : "+l"(d) : "l"(a), "l"(b));
}
__device__ __forceinline__ float unpk_sum(ull v) {
    float x, y;
    asm("mov.b64 {%0,%1}, %2;" : "=f"(x), "=f"(y) : "l"(v));
    return x + y;
}

__device__ __forceinline__ float sigm(float z) { return 1.f / (1.f + expf(-z)); }

// ===========================================================================
// Phase 1: Xg[t][b][n] = x[b][t][:] . Wx[n][:]   (x-part of all 4 gate GEMMs)
// M = B*S = 32768 (row m = b*512+t), N = 4096, K = 1024
// CTA tile 128(M) x 64(N), packed-k fp32x2 accumulation.
// ===========================================================================
#define P1_TM 128
#define P1_TN 64
#define P1_KC 32

__global__ void __launch_bounds__(256, 2) lstm_xgemm(
    const float* __restrict__ x,
    const float* __restrict__ Wf, const float* __restrict__ Wi,
    const float* __restrict__ Wc, const float* __restrict__ Wo)
{
    __shared__ float xs[P1_TM][P1_KC + 4];
    __shared__ float ws[P1_TN][P1_KC + 4];

    const int tid = threadIdx.x;
    const int m0  = blockIdx.y * P1_TM;
    const int n0  = blockIdx.x * P1_TN;            // combined gate-col index
    const int gate = n0 >> 10;
    const int hc0  = n0 & (H_ - 1);
    const float* W = (gate == 0) ? Wf : (gate == 1) ? Wi : (gate == 2) ? Wc : Wo;

    const int lane = tid & 31, warp = tid >> 5;
    const int wm = warp & 3, wn = warp >> 2;       // 4 m-warps x 2 n-warps
    const int ml = lane & 7, nl = lane >> 3;       // 8 m-lanes x 4 n-lanes

    ull acc[4][8];
#pragma unroll
    for (int i = 0; i < 4; i++)
#pragma unroll
        for (int j = 0; j < 8; j++) acc[i][j] = 0ull;

    for (int k0 = 0; k0 < E_; k0 += P1_KC) {
        // stage x tile (128x32) + W tile (64x32): 1536 float4 / 256 threads
#pragma unroll
        for (int j = 0; j < 6; j++) {
            int f = tid + j * 256;
            if (f < 1024) {
                int r = f >> 3, c = f & 7;
                float4 v = *(const float4*)(x + (size_t)(m0 + r) * E_ + k0 + c * 4);
                *(float4*)&xs[r][c * 4] = v;
            } else {
                int f2 = f - 1024;
                int r = f2 >> 3, c = f2 & 7;
                float4 v = *(const float4*)(W + (size_t)(hc0 + r) * 2048 + k0 + c * 4);
                *(float4*)&ws[r][c * 4] = v;
            }
        }
        __syncthreads();
#pragma unroll
        for (int kk = 0; kk < P1_KC; kk += 4) {
            ulonglong2 xf[4];
#pragma unroll
            for (int mj = 0; mj < 4; mj++)
                xf[mj] = *(const ulonglong2*)&xs[wm * 32 + mj * 8 + ml][kk];
#pragma unroll
            for (int nj = 0; nj < 8; nj++) {
                ulonglong2 wv = *(const ulonglong2*)&ws[wn * 32 + nj * 4 + nl][kk];
#pragma unroll
                for (int mj = 0; mj < 4; mj++) {
                    fma2(acc[mj][nj], wv.x, xf[mj].x);
                    fma2(acc[mj][nj], wv.y, xf[mj].y);
                }
            }
        }
        __syncthreads();
    }

    // epilogue -> g_xg[t][b][n]
#pragma unroll
    for (int mj = 0; mj < 4; mj++) {
        int m = m0 + wm * 32 + mj * 8 + ml;
        int b = m >> 9;              // S_ = 512
        int t = m & (S_ - 1);
        float* dst = g_xg + ((size_t)t * B_ + b) * NG;
#pragma unroll
        for (int nj = 0; nj < 8; nj++) {
            int n = n0 + wn * 32 + nj * 4 + nl;
            dst[n] = unpk_sum(acc[mj][nj]);
        }
    }
}

// ===========================================================================
// Phase 2: persistent sequential scan. 128 CTAs, CTA owns 8 hidden cols.
// Wh slice (4 gates x 8 rows x 1024) resident in SMEM for all 512 steps.
// ===========================================================================
__device__ __forceinline__ void grid_barrier() {
    __syncthreads();
    if (threadIdx.x == 0) {
        __threadfence();                                  // release
        unsigned gen = *(volatile unsigned*)&g_bar_gen;
        if (atomicAdd(&g_bar_count, 1u) == NCTA - 1) {
            atomicExch(&g_bar_count, 0u);
            __threadfence();
            atomicAdd(&g_bar_gen, 1u);
        } else {
            while (*(volatile unsigned*)&g_bar_gen == gen) __nanosleep(64);
        }
        __threadfence();                                  // acquire (invalidates L1)
    }
    __syncthreads();
}

// dynamic smem layout (bytes): Wsm 131072 | hsm 67584 | csm 2048 | bsm 128
#define P2_SMEM 200832

__global__ void __launch_bounds__(256, 1) lstm_seq(
    const float* __restrict__ Wf, const float* __restrict__ bf,
    const float* __restrict__ Wi, const float* __restrict__ bi,
    const float* __restrict__ Wc, const float* __restrict__ bc,
    const float* __restrict__ Wo, const float* __restrict__ bo,
    float* __restrict__ out)
{
    extern __shared__ float smf[];
    float* Wsm  = smf;                        // [32][1024]
    float* hsm  = smf + 32 * 1024;            // [2][64][132] (padded rows)
    float* csm  = hsm + 2 * 64 * 132;         // [64*8] cell state, SMEM-resident
    float* bsm  = csm + 512;                  // [32] biases
    ull*   red  = (ull*)hsm;                  // overlay: [32][64] k-group partials
    float* zbuf = hsm + 4096;                 // overlay: [32][64] gate preacts

    const int tid = threadIdx.x;
    const int cta = blockIdx.x;
    const float* Wp[4] = {Wf, Wi, Wc, Wo};
    const float* bp[4] = {bf, bi, bc, bo};

    // ---- one-time: load Wh slice (h-part = cols [1024,2048) of each W row)
#pragma unroll
    for (int j = 0; j < 32; j++) {
        int f = tid + j * 256;                 // 8192 float4 total
        int nl_ = f >> 8, c4 = f & 255;
        int g = nl_ >> 3, r = nl_ & 7;
        float4 v = *(const float4*)(Wp[g] + (size_t)(cta * 8 + r) * 2048 + 1024 + c4 * 4);
        *(float4*)&Wsm[nl_ * 1024 + c4 * 4] = v;
    }
    if (tid < 32) bsm[tid] = bp[tid >> 3][cta * 8 + (tid & 7)];
    for (int i = tid; i < 512; i += 256) {
        csm[i] = 0.f;
        int b = i >> 3, r = i & 7;
        g_h[0][b * H_ + cta * 8 + r] = 0.f;    // h0 = 0 (this CTA's columns)
    }
    grid_barrier();

    const int lane = tid & 31;
    const int warp = tid >> 5;
    const int kg = warp >> 2;                  // split-K group: k<512 / k>=512
    const int g  = warp & 3;                   // gate handled by this warp
    const int b0 = lane, b1 = lane + 32;
    const int tg = tid & 127;

    for (int t = 0; t < S_; t++) {
        const float* hcur = g_h[t & 1];
        ull acc[8][2];
#pragma unroll
        for (int r = 0; r < 8; r++) { acc[r][0] = 0ull; acc[r][1] = 0ull; }

#pragma unroll 1
        for (int ch = 0; ch < 4; ch++) {
            const int kb = kg * 512 + ch * 128;
            // stage h chunk [64][128] for this k-group (L2 -> SMEM, L1-bypass)
#pragma unroll
            for (int j = 0; j < 16; j++) {
                int f = tg + j * 128;
                int bb = f >> 5, c4 = f & 31;
                float4 v = __ldcg((const float4*)(hcur + bb * H_ + kb + c4 * 4));
                *(float4*)&hsm[(kg * 64 + bb) * 132 + c4 * 4] = v;
            }
            __syncthreads();
            const float* hb = hsm + kg * 64 * 132;
            const float* wb = Wsm + g * 8 * 1024 + kb;
#pragma unroll 8
            for (int kk = 0; kk < 128; kk += 4) {
                ulonglong2 h0 = *(const ulonglong2*)(hb + b0 * 132 + kk);
                ulonglong2 h1 = *(const ulonglong2*)(hb + b1 * 132 + kk);
#pragma unroll
                for (int r = 0; r < 8; r++) {
                    ulonglong2 wv = *(const ulonglong2*)(wb + r * 1024 + kk);
                    fma2(acc[r][0], wv.x, h0.x);
                    fma2(acc[r][0], wv.y, h0.y);
                    fma2(acc[r][1], wv.x, h1.x);
                    fma2(acc[r][1], wv.y, h1.y);
                }
            }
            __syncthreads();
        }

        // ---- reduce split-K groups (hsm region reused as scratch)
        if (kg == 1) {
#pragma unroll
            for (int r = 0; r < 8; r++) {
                red[(g * 8 + r) * 64 + b0] = acc[r][0];
                red[(g * 8 + r) * 64 + b1] = acc[r][1];
            }
        }
        __syncthreads();
        if (kg == 0) {
            const float* xg = g_xg + (size_t)t * B_ * NG + g * 1024 + cta * 8;
#pragma unroll
            for (int r = 0; r < 8; r++) {
                int nl_ = g * 8 + r;
                float z0 = unpk_sum(acc[r][0]) + unpk_sum(red[nl_ * 64 + b0])
                         + bsm[nl_] + __ldg(xg + (size_t)b0 * NG + r);
                float z1 = unpk_sum(acc[r][1]) + unpk_sum(red[nl_ * 64 + b1])
                         + bsm[nl_] + __ldg(xg + (size_t)b1 * NG + r);
                zbuf[nl_ * 64 + b0] = z0;
                zbuf[nl_ * 64 + b1] = z1;
            }
        }
        __syncthreads();

        // ---- elementwise gate math, c stays in SMEM, h -> global + output
        float* hnext = g_h[(t + 1) & 1];
        for (int i = tid; i < 512; i += 256) {
            int b = i >> 3, r = i & 7;
            float zf = zbuf[(0  + r) * 64 + b];
            float zi = zbuf[(8  + r) * 64 + b];
            float zg = zbuf[(16 + r) * 64 + b];
            float zo = zbuf[(24 + r) * 64 + b];
            float fg = sigm(zf);
            float ig = sigm(zi);
            float gg = tanhf(zg);
            float og = sigm(zo);
            float c  = fg * csm[i] + ig * gg;
            csm[i] = c;
            float h = og * tanhf(c);
            int hc = cta * 8 + r;
            hnext[b * H_ + hc] = h;
            out[((size_t)b * S_ + t) * H_ + hc] = h;
            if (t == S_ - 1) {
                out[(size_t)B_ * S_ * H_ + b * H_ + hc] = h;                 // hT
                out[(size_t)B_ * S_ * H_ + (size_t)B_ * H_ + b * H_ + hc] = c; // cT
            }
        }
        grid_barrier();
    }
}

// ===========================================================================
extern "C" void kernel_launch(void* const* d_in, const int* in_sizes, int n_in,
                              void* d_out, int out_size) {
    const float* x  = (const float*)d_in[0];
    const float* Wf = (const float*)d_in[1];
    const float* bf = (const float*)d_in[2];
    const float* Wi = (const float*)d_in[3];
    const float* bi = (const float*)d_in[4];
    const float* Wc = (const float*)d_in[5];
    const float* bc = (const float*)d_in[6];
    const float* Wo = (const float*)d_in[7];
    const float* bo = (const float*)d_in[8];
    float* out = (float*)d_out;

    dim3 g1(NG / P1_TN, (B_ * S_) / P1_TM);   // (64, 256)
    lstm_xgemm<<<g1, 256>>>(x, Wf, Wi, Wc, Wo);

    cudaFuncSetAttribute(lstm_seq, cudaFuncAttributeMaxDynamicSharedMemorySize, P2_SMEM);
    lstm_seq<<<NCTA, 256, P2_SMEM>>>(Wf, bf, Wi, bi, Wc, bc, Wo, bo, out);
}

// round 5
// speedup vs baseline: 1.7887x; 1.7887x over previous
#include <cuda_runtime.h>
#include <cstdint>
#include <cstddef>

#define B_  64
#define S_  512
#define E_  1024
#define H_  1024
#define NG  4096
#define NCTA 128

// ---------------- device scratch ----------------
__device__ float g_xg[(size_t)S_ * B_ * NG];   // [t][b][n]
__device__ float g_h[2][B_ * H_];              // hidden double buffer [b][k]
__device__ unsigned g_bar_count = 0;
__device__ unsigned g_bar_gen   = 0;

// ---------------- helpers ----------------
__device__ __forceinline__ uint32_t f2tf(float f) {   // round-to-nearest tf32
    uint32_t r; asm("cvt.rna.tf32.f32 %0, %1;" : "=r"(r) : "f"(f)); return r;
}
// D += A(16x8, tf32) * B(8x8, tf32), fp32 accum. Baseline sm_80+ instruction.
__device__ __forceinline__ void mma8(float* d, const uint32_t* a, const uint32_t* b) {
    asm("mma.sync.aligned.m16n8k8.row.col.f32.tf32.tf32.f32 "
        "{%0,%1,%2,%3}, {%4,%5,%6,%7}, {%8,%9}, {%0,%1,%2,%3};"
        : "+f"(d[0]), "+f"(d[1]), "+f"(d[2]), "+f"(d[3])
        : "r"(a[0]), "r"(a[1]), "r"(a[2]), "r"(a[3]), "r"(b[0]), "r"(b[1]));
}
__device__ __forceinline__ float sigm(float z) { return 1.f / (1.f + expf(-z)); }

__device__ __forceinline__ void grid_barrier() {
    __syncthreads();
    if (threadIdx.x == 0) {
        __threadfence();
        unsigned gen = *(volatile unsigned*)&g_bar_gen;
        if (atomicAdd(&g_bar_count, 1u) == NCTA - 1) {
            atomicExch(&g_bar_count, 0u);
            __threadfence();
            atomicAdd(&g_bar_gen, 1u);
        } else {
            while (*(volatile unsigned*)&g_bar_gen == gen) __nanosleep(64);
        }
        __threadfence();
    }
    __syncthreads();
}

// ===========================================================================
// Phase 1: Xg = x @ Wx^T (all 4 gates), tf32 mma.sync.
// CTA tile 128x128, K chunks of 32. 8 warps = 2(M) x 4(N), warp tile 64x32.
// ===========================================================================
__global__ void __launch_bounds__(256) xgemm_mma(
    const float* __restrict__ x,
    const float* __restrict__ Wf, const float* __restrict__ Wi,
    const float* __restrict__ Wc, const float* __restrict__ Wo)
{
    __shared__ uint32_t As[128 * 36];    // stride 36: frag LDS provably conflict-free
    __shared__ uint32_t Bs[128 * 36];

    const int tid = threadIdx.x;
    const int wid = tid >> 5, lane = tid & 31;
    const int gid = lane >> 2, tg = lane & 3;
    const int wm = wid >> 2, wn = wid & 3;
    const int m0 = blockIdx.y * 128;
    const int n0 = blockIdx.x * 128;
    const int gate = n0 >> 10;
    const int hc0 = n0 & (H_ - 1);
    const float* W = (gate == 0) ? Wf : (gate == 1) ? Wi : (gate == 2) ? Wc : Wo;

    float acc[4][4][4];
#pragma unroll
    for (int i = 0; i < 4; i++)
#pragma unroll
        for (int j = 0; j < 4; j++)
#pragma unroll
            for (int k = 0; k < 4; k++) acc[i][j][k] = 0.f;

    float4 pA[4], pB[4];
    const int sr = tid >> 3, sc4 = tid & 7;              // staging row / float4-col
#pragma unroll
    for (int j = 0; j < 4; j++) {
        int r = sr + j * 32;
        pA[j] = *(const float4*)(x + (size_t)(m0 + r) * E_ + sc4 * 4);
        pB[j] = *(const float4*)(W + (size_t)(hc0 + r) * 2048 + sc4 * 4);
    }

    for (int ch = 0; ch < 32; ch++) {
        float4 cA[4], cB[4];
#pragma unroll
        for (int j = 0; j < 4; j++) { cA[j] = pA[j]; cB[j] = pB[j]; }
        if (ch < 31) {
            const int k0 = (ch + 1) * 32;
#pragma unroll
            for (int j = 0; j < 4; j++) {
                int r = sr + j * 32;
                pA[j] = *(const float4*)(x + (size_t)(m0 + r) * E_ + k0 + sc4 * 4);
                pB[j] = *(const float4*)(W + (size_t)(hc0 + r) * 2048 + k0 + sc4 * 4);
            }
        }
        __syncthreads();                                  // prev compute done
#pragma unroll
        for (int j = 0; j < 4; j++) {
            int r = sr + j * 32;
            uint4 ua = make_uint4(f2tf(cA[j].x), f2tf(cA[j].y), f2tf(cA[j].z), f2tf(cA[j].w));
            uint4 ub = make_uint4(f2tf(cB[j].x), f2tf(cB[j].y), f2tf(cB[j].z), f2tf(cB[j].w));
            *(uint4*)&As[r * 36 + sc4 * 4] = ua;
            *(uint4*)&Bs[r * 36 + sc4 * 4] = ub;
        }
        __syncthreads();
#pragma unroll
        for (int kk = 0; kk < 32; kk += 8) {
            uint32_t af[4][4], bf[4][2];
#pragma unroll
            for (int mi = 0; mi < 4; mi++) {
                int r = wm * 64 + mi * 16 + gid;
                af[mi][0] = As[r * 36 + kk + tg];
                af[mi][1] = As[(r + 8) * 36 + kk + tg];
                af[mi][2] = As[r * 36 + kk + tg + 4];
                af[mi][3] = As[(r + 8) * 36 + kk + tg + 4];
            }
#pragma unroll
            for (int ni = 0; ni < 4; ni++) {
                int n = wn * 32 + ni * 8 + gid;
                bf[ni][0] = Bs[n * 36 + kk + tg];
                bf[ni][1] = Bs[n * 36 + kk + tg + 4];
            }
#pragma unroll
            for (int mi = 0; mi < 4; mi++)
#pragma unroll
                for (int ni = 0; ni < 4; ni++)
                    mma8(acc[mi][ni], af[mi], bf[ni]);
        }
    }

    // epilogue: frags -> g_xg[t][b][n]
#pragma unroll
    for (int mi = 0; mi < 4; mi++) {
        int row = m0 + wm * 64 + mi * 16 + gid;
        int b = row >> 9, t = row & (S_ - 1);           // row = b*512 + t
#pragma unroll
        for (int ni = 0; ni < 4; ni++) {
            int col = n0 + wn * 32 + ni * 8 + tg * 2;
            float* p0 = g_xg + ((size_t)t * B_ + b) * NG + col;
            float* p1 = g_xg + ((size_t)(t + 8) * B_ + b) * NG + col;
            *(float2*)p0 = make_float2(acc[mi][ni][0], acc[mi][ni][1]);
            *(float2*)p1 = make_float2(acc[mi][ni][2], acc[mi][ni][3]);
        }
    }
}

// ===========================================================================
// Phase 2: persistent scan, tf32 mma.sync.
// CTA owns 32 gate-cols (4 gates x 8 cols). Wh resident in SMEM in B-frag
// order. h staged per 64-k chunk into A-frag order (double buffered).
// Warps: (mg in 0..1) x (kg in 0..3), split-K interleaved within each chunk.
// ===========================================================================
#define WB_OFF 0            // 131072 B : B-frags [ni][ks 128][lane]{b0,b1}
#define AB_OFF 131072       // 32768 B  : 2 x A-frag chunk buffers
#define RED_OFF AB_OFF      // reuse    : 3 x [64][34] fp32 split-K partials
#define ZB_OFF 163840       // 8704 B   : [64][34] fp32 z
#define CS_OFF 172544       // 2048 B   : cell state [64][8]
#define BS_OFF 174592       // 128 B    : biases
#define P2_SMEM 174720

__global__ void __launch_bounds__(256, 1) lstm_seq_mma(
    const float* __restrict__ Wf, const float* __restrict__ bf,
    const float* __restrict__ Wi, const float* __restrict__ bi,
    const float* __restrict__ Wc, const float* __restrict__ bc,
    const float* __restrict__ Wo, const float* __restrict__ bo,
    float* __restrict__ out)
{
    extern __shared__ char sm[];
    uint32_t* wb  = (uint32_t*)(sm + WB_OFF);
    uint32_t* ab  = (uint32_t*)(sm + AB_OFF);
    float*    red = (float*)(sm + RED_OFF);
    float*    zbf = (float*)(sm + ZB_OFF);
    float*    csm = (float*)(sm + CS_OFF);
    float*    bsm = (float*)(sm + BS_OFF);

    const int tid = threadIdx.x;
    const int wid = tid >> 5, lane = tid & 31;
    const int gid = lane >> 2, tg = lane & 3;
    const int kg = wid & 3, mg = wid >> 2;
    const int cta = blockIdx.x;
    const float* Wp[4] = {Wf, Wi, Wc, Wo};
    const float* bp[4] = {bf, bi, bc, bo};

    // one-time: Wh -> SMEM in B-fragment order (tf32-rounded)
    for (int s = tid; s < 16384; s += 256) {
        int ng = s >> 12, ks = (s >> 5) & 127, l = s & 31;
        const float* wr = Wp[ng] + (size_t)(cta * 8 + (l >> 2)) * 2048 + 1024 + ks * 8 + (l & 3);
        wb[s * 2]     = f2tf(wr[0]);
        wb[s * 2 + 1] = f2tf(wr[4]);
    }
    if (tid < 32) bsm[tid] = bp[tid >> 3][cta * 8 + (tid & 7)];
    for (int i = tid; i < 512; i += 256) {
        csm[i] = 0.f;
        g_h[0][cta * 512 + i] = 0.f;
    }
    __syncthreads();
    grid_barrier();

    const int sr = tid >> 4, sc4 = tid & 15;             // staging: row, float4-col

    for (int t = 0; t < S_; t++) {
        const float* hcur = g_h[t & 1];
        float acc[2][4][4];
#pragma unroll
        for (int i = 0; i < 2; i++)
#pragma unroll
            for (int j = 0; j < 4; j++)
#pragma unroll
                for (int k = 0; k < 4; k++) acc[i][j][k] = 0.f;

        float4 pf[4];
#pragma unroll
        for (int j = 0; j < 4; j++) {
            int r = sr + j * 16;
            pf[j] = __ldcg((const float4*)(hcur + r * H_ + sc4 * 4));
        }

        for (int ch = 0; ch < 16; ch++) {
            float4 cur[4];
#pragma unroll
            for (int j = 0; j < 4; j++) cur[j] = pf[j];
            if (ch < 15) {
                const int kb = (ch + 1) * 64;
#pragma unroll
                for (int j = 0; j < 4; j++) {
                    int r = sr + j * 16;
                    pf[j] = __ldcg((const float4*)(hcur + r * H_ + kb + sc4 * 4));
                }
            }
            // stage cur into A-frag layout
            const int bb = (ch & 1) * 4096;
            const int ks_s = sc4 >> 1;
            const int sk2 = (sc4 & 1) << 1;
#pragma unroll
            for (int j = 0; j < 4; j++) {
                int r = sr + j * 16;
                int mi = r >> 4;
                int lb = (r & 7) << 2;
                int slot = ((r >> 3) & 1) | sk2;
                int fb = bb + ((ks_s * 4 + mi) * 32) * 4 + slot;
                float v[4] = {cur[j].x, cur[j].y, cur[j].z, cur[j].w};
#pragma unroll
                for (int ii = 0; ii < 4; ii++) {
                    int lp = (lb + ii + ks_s) & 31;
                    ab[fb + lp * 4 - slot + slot] = 0;   // placeholder removed below
                    ab[bb + ((ks_s * 4 + mi) * 32 + lp) * 4 + slot] = f2tf(v[ii]);
                }
            }
            __syncthreads();
            // compute: warp (mg, kg) does ksteps {kg, kg+4} of this chunk
            const uint32_t* abB = ab + (ch & 1) * 4096;
#pragma unroll
            for (int s = 0; s < 2; s++) {
                const int ks = kg + s * 4;
                const int ksg = ch * 8 + ks;
                const int lp = (lane + ks) & 31;
                uint32_t af[2][4];
#pragma unroll
                for (int m2 = 0; m2 < 2; m2++) {
                    int mi = mg * 2 + m2;
                    uint4 v = *(const uint4*)&abB[((ks * 4 + mi) * 32 + lp) * 4];
                    af[m2][0] = v.x; af[m2][1] = v.y; af[m2][2] = v.z; af[m2][3] = v.w;
                }
                uint32_t bfr[4][2];
#pragma unroll
                for (int ni = 0; ni < 4; ni++) {
                    uint2 w2 = *(const uint2*)&wb[((ni * 128 + ksg) * 32 + lane) * 2];
                    bfr[ni][0] = w2.x; bfr[ni][1] = w2.y;
                }
#pragma unroll
                for (int m2 = 0; m2 < 2; m2++)
#pragma unroll
                    for (int ni = 0; ni < 4; ni++)
                        mma8(acc[m2][ni], af[m2], bfr[ni]);
            }
            __syncthreads();
        }

        // split-K reduction through SMEM (red overlays ab; all compute done)
        if (kg != 0) {
#pragma unroll
            for (int m2 = 0; m2 < 2; m2++)
#pragma unroll
                for (int ni = 0; ni < 4; ni++) {
                    int r0 = mg * 32 + m2 * 16 + gid;
                    int c0 = ni * 8 + tg * 2;
                    float* rp = red + ((kg - 1) * 64 + r0) * 34 + c0;
                    *(float2*)rp             = make_float2(acc[m2][ni][0], acc[m2][ni][1]);
                    *(float2*)(rp + 8 * 34)  = make_float2(acc[m2][ni][2], acc[m2][ni][3]);
                }
        }
        __syncthreads();
        if (kg == 0) {
#pragma unroll
            for (int m2 = 0; m2 < 2; m2++)
#pragma unroll
                for (int ni = 0; ni < 4; ni++) {
                    int r0 = mg * 32 + m2 * 16 + gid;
                    int c0 = ni * 8 + tg * 2;
                    float2 z01 = make_float2(acc[m2][ni][0], acc[m2][ni][1]);
                    float2 z23 = make_float2(acc[m2][ni][2], acc[m2][ni][3]);
#pragma unroll
                    for (int p = 0; p < 3; p++) {
                        float2 a = *(float2*)(red + (p * 64 + r0) * 34 + c0);
                        float2 b2 = *(float2*)(red + (p * 64 + r0 + 8) * 34 + c0);
                        z01.x += a.x;  z01.y += a.y;
                        z23.x += b2.x; z23.y += b2.y;
                    }
                    *(float2*)(zbf + r0 * 34 + c0)       = z01;
                    *(float2*)(zbf + (r0 + 8) * 34 + c0) = z23;
                }
        }
        __syncthreads();

        // gate math; c stays in SMEM
        float* hnext = g_h[(t + 1) & 1];
        for (int i = tid; i < 512; i += 256) {
            int b = i >> 3, r = i & 7;
            const float* xgb = g_xg + ((size_t)t * B_ + b) * NG + cta * 8 + r;
            float zf = zbf[b * 34 + r]      + bsm[r]      + __ldg(xgb);
            float zi = zbf[b * 34 + 8 + r]  + bsm[8 + r]  + __ldg(xgb + 1024);
            float zg = zbf[b * 34 + 16 + r] + bsm[16 + r] + __ldg(xgb + 2048);
            float zo = zbf[b * 34 + 24 + r] + bsm[24 + r] + __ldg(xgb + 3072);
            float cc = sigm(zf) * csm[i] + sigm(zi) * tanhf(zg);
            csm[i] = cc;
            float h = sigm(zo) * tanhf(cc);
            int hc = cta * 8 + r;
            hnext[b * H_ + hc] = h;
            out[((size_t)b * S_ + t) * H_ + hc] = h;
            if (t == S_ - 1) {
                out[(size_t)B_ * S_ * H_ + b * H_ + hc] = h;                   // hT
                out[(size_t)B_ * S_ * H_ + (size_t)B_ * H_ + b * H_ + hc] = cc; // cT
            }
        }
        grid_barrier();
    }
}

// ===========================================================================
extern "C" void kernel_launch(void* const* d_in, const int* in_sizes, int n_in,
                              void* d_out, int out_size) {
    const float* x  = (const float*)d_in[0];
    const float* Wf = (const float*)d_in[1];
    const float* bf = (const float*)d_in[2];
    const float* Wi = (const float*)d_in[3];
    const float* bi = (const float*)d_in[4];
    const float* Wc = (const float*)d_in[5];
    const float* bc = (const float*)d_in[6];
    const float* Wo = (const float*)d_in[7];
    const float* bo = (const float*)d_in[8];
    float* out = (float*)d_out;

    dim3 g1(NG / 128, (B_ * S_) / 128);            // (32, 256)
    xgemm_mma<<<g1, 256>>>(x, Wf, Wi, Wc, Wo);

    cudaFuncSetAttribute(lstm_seq_mma, cudaFuncAttributeMaxDynamicSharedMemorySize, P2_SMEM);
    lstm_seq_mma<<<NCTA, 256, P2_SMEM>>>(Wf, bf, Wi, bi, Wc, bc, Wo, bo, out);
}

// round 6
// speedup vs baseline: 2.2314x; 1.2475x over previous
#include <cuda_runtime.h>
#include <cstdint>
#include <cstddef>

#define B_  64
#define S_  512
#define E_  1024
#define H_  1024
#define NG  4096
#define NCTA 128

// ---------------- device scratch ----------------
__device__ float g_xg[(size_t)S_ * B_ * NG];   // [t][b][n]
__device__ float g_h[2][B_ * H_];              // hidden double buffer [b][k]
__device__ unsigned g_bar_count = 0;
__device__ unsigned g_bar_gen   = 0;

// ---------------- helpers ----------------
__device__ __forceinline__ uint32_t f2tf(float f) {   // round-to-nearest tf32
    uint32_t r; asm("cvt.rna.tf32.f32 %0, %1;" : "=r"(r) : "f"(f)); return r;
}
__device__ __forceinline__ void mma8(float* d, const uint32_t* a, const uint32_t* b) {
    asm("mma.sync.aligned.m16n8k8.row.col.f32.tf32.tf32.f32 "
        "{%0,%1,%2,%3}, {%4,%5,%6,%7}, {%8,%9}, {%0,%1,%2,%3};"
        : "+f"(d[0]), "+f"(d[1]), "+f"(d[2]), "+f"(d[3])
        : "r"(a[0]), "r"(a[1]), "r"(a[2]), "r"(a[3]), "r"(b[0]), "r"(b[1]));
}
__device__ __forceinline__ uint32_t smem_u32(const void* p) {
    uint32_t a;
    asm("{ .reg .u64 t; cvta.to.shared.u64 t, %1; cvt.u32.u64 %0, t; }" : "=r"(a) : "l"(p));
    return a;
}
__device__ __forceinline__ void cpa16(uint32_t saddr, const void* g) {
    asm volatile("cp.async.cg.shared.global [%0], [%1], 16;" :: "r"(saddr), "l"(g) : "memory");
}
__device__ __forceinline__ void cpa_commit() {
    asm volatile("cp.async.commit_group;" ::: "memory");
}
template<int N> __device__ __forceinline__ void cpa_wait() {
    asm volatile("cp.async.wait_group %0;" :: "n"(N) : "memory");
}
__device__ __forceinline__ float sigm(float z) { return 1.f / (1.f + expf(-z)); }

__device__ __forceinline__ void grid_barrier() {
    __syncthreads();
    if (threadIdx.x == 0) {
        __threadfence();
        unsigned gen = *(volatile unsigned*)&g_bar_gen;
        if (atomicAdd(&g_bar_count, 1u) == NCTA - 1) {
            atomicExch(&g_bar_count, 0u);
            __threadfence();
            atomicAdd(&g_bar_gen, 1u);
        } else {
            while (*(volatile unsigned*)&g_bar_gen == gen) __nanosleep(64);
        }
        __threadfence();
    }
    __syncthreads();
}

// ===========================================================================
// Phase 1: Xg = x @ Wx^T (all 4 gates), tf32 mma.sync, cp.async 3-stage pipe.
// CTA tile 128x128, K chunks of 32. 8 warps = 2(M) x 4(N), warp tile 64x32.
// SMEM per stage: A[128][36] + B[128][36] raw fp32 (cvt at frag load).
// ===========================================================================
#define P1_STRIDE 9216               // floats per stage (2 * 128 * 36)
#define P1_SMEM   (3 * P1_STRIDE * 4)

__device__ __forceinline__ void p1_issue(float* smf, int st,
    const float* x, const float* W, int m0, int hc0, int k0, int tid)
{
    float* A = smf + st * P1_STRIDE;
    float* Bp = A + 4608;
    const int r = tid >> 3, c4 = tid & 7;
#pragma unroll
    for (int j = 0; j < 4; j++) {
        int rr = r + j * 32;
        cpa16(smem_u32(&A[rr * 36 + c4 * 4]),  x + (size_t)(m0 + rr) * E_ + k0 + c4 * 4);
        cpa16(smem_u32(&Bp[rr * 36 + c4 * 4]), W + (size_t)(hc0 + rr) * 2048 + k0 + c4 * 4);
    }
    cpa_commit();
}

__global__ void __launch_bounds__(256, 2) xgemm_mma(
    const float* __restrict__ x,
    const float* __restrict__ Wf, const float* __restrict__ Wi,
    const float* __restrict__ Wc, const float* __restrict__ Wo)
{
    extern __shared__ float smf[];

    const int tid = threadIdx.x;
    const int wid = tid >> 5, lane = tid & 31;
    const int gid = lane >> 2, tg = lane & 3;
    const int wm = wid >> 2, wn = wid & 3;
    const int m0 = blockIdx.y * 128;
    const int n0 = blockIdx.x * 128;
    const int gate = n0 >> 10;
    const int hc0 = n0 & (H_ - 1);
    const float* W = (gate == 0) ? Wf : (gate == 1) ? Wi : (gate == 2) ? Wc : Wo;

    float acc[4][4][4];
#pragma unroll
    for (int i = 0; i < 4; i++)
#pragma unroll
        for (int j = 0; j < 4; j++)
#pragma unroll
            for (int k = 0; k < 4; k++) acc[i][j][k] = 0.f;

    p1_issue(smf, 0, x, W, m0, hc0, 0, tid);
    p1_issue(smf, 1, x, W, m0, hc0, 32, tid);

    int st = 0;
    for (int ch = 0; ch < 32; ch++) {
        if (ch < 31) cpa_wait<1>(); else cpa_wait<0>();
        __syncthreads();
        if (ch + 2 < 32) {
            int st2 = st + 2; if (st2 >= 3) st2 -= 3;
            p1_issue(smf, st2, x, W, m0, hc0, (ch + 2) * 32, tid);
        }
        const float* As  = smf + st * P1_STRIDE;
        const float* Bsf = As + 4608;
#pragma unroll
        for (int kk = 0; kk < 32; kk += 8) {
            uint32_t af[4][4], bf[4][2];
#pragma unroll
            for (int mi = 0; mi < 4; mi++) {
                int r = wm * 64 + mi * 16 + gid;
                af[mi][0] = f2tf(As[r * 36 + kk + tg]);
                af[mi][1] = f2tf(As[(r + 8) * 36 + kk + tg]);
                af[mi][2] = f2tf(As[r * 36 + kk + tg + 4]);
                af[mi][3] = f2tf(As[(r + 8) * 36 + kk + tg + 4]);
            }
#pragma unroll
            for (int ni = 0; ni < 4; ni++) {
                int n = wn * 32 + ni * 8 + gid;
                bf[ni][0] = f2tf(Bsf[n * 36 + kk + tg]);
                bf[ni][1] = f2tf(Bsf[n * 36 + kk + tg + 4]);
            }
#pragma unroll
            for (int mi = 0; mi < 4; mi++)
#pragma unroll
                for (int ni = 0; ni < 4; ni++)
                    mma8(acc[mi][ni], af[mi], bf[ni]);
        }
        if (++st >= 3) st -= 3;
    }

    // epilogue: frags -> g_xg[t][b][n]
#pragma unroll
    for (int mi = 0; mi < 4; mi++) {
        int row = m0 + wm * 64 + mi * 16 + gid;
        int b = row >> 9, t = row & (S_ - 1);           // row = b*512 + t
#pragma unroll
        for (int ni = 0; ni < 4; ni++) {
            int col = n0 + wn * 32 + ni * 8 + tg * 2;
            float* p0 = g_xg + ((size_t)t * B_ + b) * NG + col;
            float* p1 = g_xg + ((size_t)(t + 8) * B_ + b) * NG + col;
            *(float2*)p0 = make_float2(acc[mi][ni][0], acc[mi][ni][1]);
            *(float2*)p1 = make_float2(acc[mi][ni][2], acc[mi][ni][3]);
        }
    }
}

// ===========================================================================
// Phase 2: persistent scan, tf32 mma.sync, cp.async h staging (3 buffers).
// CTA owns 32 gate-cols. Wh resident in SMEM in B-frag order (tf32).
// h chunks staged raw fp32 into [64][68]; cvt at A-frag load.
// Warps: (mg 0..1) x (kg 0..3) split-K, reduced through SMEM.
// ===========================================================================
#define WB_OFF  0                            // 131072 B
#define AB_OFF  131072                       // 3 x 64 x 68 x 4 = 52224 B
#define RED_OFF (AB_OFF + 52224)             // 3 x [64][34] = 26112 B
#define ZB_OFF  (RED_OFF + 26112)            // [64][34] = 8704 B
#define CS_OFF  (ZB_OFF + 8704)              // 2048 B
#define BS_OFF  (CS_OFF + 2048)              // 128 B
#define P2_SMEM (BS_OFF + 128)               // 220288 B

__device__ __forceinline__ void p2_issue(const float* hcur, float* ab, int buf, int kb, int tid) {
    float* A = ab + buf * (64 * 68);
    const int r = tid >> 4, c4 = tid & 15;
#pragma unroll
    for (int j = 0; j < 4; j++) {
        int rr = r + j * 16;
        cpa16(smem_u32(&A[rr * 68 + c4 * 4]), hcur + rr * H_ + kb + c4 * 4);
    }
    cpa_commit();
}

__global__ void __launch_bounds__(256, 1) lstm_seq_mma(
    const float* __restrict__ Wf, const float* __restrict__ bf,
    const float* __restrict__ Wi, const float* __restrict__ bi,
    const float* __restrict__ Wc, const float* __restrict__ bc,
    const float* __restrict__ Wo, const float* __restrict__ bo,
    float* __restrict__ out)
{
    extern __shared__ char sm[];
    uint32_t* wb  = (uint32_t*)(sm + WB_OFF);
    float*    ab  = (float*)(sm + AB_OFF);
    float*    red = (float*)(sm + RED_OFF);
    float*    zbf = (float*)(sm + ZB_OFF);
    float*    csm = (float*)(sm + CS_OFF);
    float*    bsm = (float*)(sm + BS_OFF);

    const int tid = threadIdx.x;
    const int wid = tid >> 5, lane = tid & 31;
    const int gid = lane >> 2, tg = lane & 3;
    const int kg = wid & 3, mg = wid >> 2;
    const int cta = blockIdx.x;
    const float* Wp[4] = {Wf, Wi, Wc, Wo};
    const float* bp[4] = {bf, bi, bc, bo};

    // one-time: Wh -> SMEM in B-fragment order (tf32-rounded)
    for (int s = tid; s < 16384; s += 256) {
        int ng = s >> 12, ks = (s >> 5) & 127, l = s & 31;
        const float* wr = Wp[ng] + (size_t)(cta * 8 + (l >> 2)) * 2048 + 1024 + ks * 8 + (l & 3);
        wb[s * 2]     = f2tf(wr[0]);
        wb[s * 2 + 1] = f2tf(wr[4]);
    }
    if (tid < 32) bsm[tid] = bp[tid >> 3][cta * 8 + (tid & 7)];
    for (int i = tid; i < 512; i += 256) {
        csm[i] = 0.f;
        g_h[0][cta * 512 + i] = 0.f;
    }
    __syncthreads();
    grid_barrier();

    for (int t = 0; t < S_; t++) {
        const float* hcur = g_h[t & 1];
        float acc[2][4][4];
#pragma unroll
        for (int i = 0; i < 2; i++)
#pragma unroll
            for (int j = 0; j < 4; j++)
#pragma unroll
                for (int k = 0; k < 4; k++) acc[i][j][k] = 0.f;

        p2_issue(hcur, ab, 0, 0, tid);
        int buf = 0;
        for (int ch = 0; ch < 16; ch++) {
            if (ch < 15) {
                int b2 = buf + 1; if (b2 >= 3) b2 -= 3;
                p2_issue(hcur, ab, b2, (ch + 1) * 64, tid);
                cpa_wait<1>();
            } else {
                cpa_wait<0>();
            }
            __syncthreads();
            const float* A = ab + buf * (64 * 68);
#pragma unroll
            for (int s = 0; s < 2; s++) {
                const int ks = kg + s * 4;
                const int ksg = ch * 8 + ks;
                uint32_t af[2][4];
#pragma unroll
                for (int m2 = 0; m2 < 2; m2++) {
                    int r = mg * 32 + m2 * 16 + gid;
                    af[m2][0] = f2tf(A[r * 68 + ks * 8 + tg]);
                    af[m2][1] = f2tf(A[(r + 8) * 68 + ks * 8 + tg]);
                    af[m2][2] = f2tf(A[r * 68 + ks * 8 + tg + 4]);
                    af[m2][3] = f2tf(A[(r + 8) * 68 + ks * 8 + tg + 4]);
                }
                uint32_t bfr[4][2];
#pragma unroll
                for (int ni = 0; ni < 4; ni++) {
                    uint2 w2 = *(const uint2*)&wb[((ni * 128 + ksg) * 32 + lane) * 2];
                    bfr[ni][0] = w2.x; bfr[ni][1] = w2.y;
                }
#pragma unroll
                for (int m2 = 0; m2 < 2; m2++)
#pragma unroll
                    for (int ni = 0; ni < 4; ni++)
                        mma8(acc[m2][ni], af[m2], bfr[ni]);
            }
            if (++buf >= 3) buf -= 3;
        }

        // split-K reduction through SMEM
        if (kg != 0) {
#pragma unroll
            for (int m2 = 0; m2 < 2; m2++)
#pragma unroll
                for (int ni = 0; ni < 4; ni++) {
                    int r0 = mg * 32 + m2 * 16 + gid;
                    int c0 = ni * 8 + tg * 2;
                    float* rp = red + ((kg - 1) * 64 + r0) * 34 + c0;
                    *(float2*)rp            = make_float2(acc[m2][ni][0], acc[m2][ni][1]);
                    *(float2*)(rp + 8 * 34) = make_float2(acc[m2][ni][2], acc[m2][ni][3]);
                }
        }
        __syncthreads();
        if (kg == 0) {
#pragma unroll
            for (int m2 = 0; m2 < 2; m2++)
#pragma unroll
                for (int ni = 0; ni < 4; ni++) {
                    int r0 = mg * 32 + m2 * 16 + gid;
                    int c0 = ni * 8 + tg * 2;
                    float2 z01 = make_float2(acc[m2][ni][0], acc[m2][ni][1]);
                    float2 z23 = make_float2(acc[m2][ni][2], acc[m2][ni][3]);
#pragma unroll
                    for (int p = 0; p < 3; p++) {
                        float2 a  = *(float2*)(red + (p * 64 + r0) * 34 + c0);
                        float2 b2 = *(float2*)(red + (p * 64 + r0 + 8) * 34 + c0);
                        z01.x += a.x;  z01.y += a.y;
                        z23.x += b2.x; z23.y += b2.y;
                    }
                    *(float2*)(zbf + r0 * 34 + c0)       = z01;
                    *(float2*)(zbf + (r0 + 8) * 34 + c0) = z23;
                }
        }
        __syncthreads();

        // gate math; c stays in SMEM
        float* hnext = g_h[(t + 1) & 1];
        for (int i = tid; i < 512; i += 256) {
            int b = i >> 3, r = i & 7;
            const float* xgb = g_xg + ((size_t)t * B_ + b) * NG + cta * 8 + r;
            float zf = zbf[b * 34 + r]      + bsm[r]      + __ldg(xgb);
            float zi = zbf[b * 34 + 8 + r]  + bsm[8 + r]  + __ldg(xgb + 1024);
            float zg = zbf[b * 34 + 16 + r] + bsm[16 + r] + __ldg(xgb + 2048);
            float zo = zbf[b * 34 + 24 + r] + bsm[24 + r] + __ldg(xgb + 3072);
            float cc = sigm(zf) * csm[i] + sigm(zi) * tanhf(zg);
            csm[i] = cc;
            float h = sigm(zo) * tanhf(cc);
            int hc = cta * 8 + r;
            hnext[b * H_ + hc] = h;
            out[((size_t)b * S_ + t) * H_ + hc] = h;
            if (t == S_ - 1) {
                out[(size_t)B_ * S_ * H_ + b * H_ + hc] = h;                    // hT
                out[(size_t)B_ * S_ * H_ + (size_t)B_ * H_ + b * H_ + hc] = cc; // cT
            }
        }
        grid_barrier();
    }
}

// ===========================================================================
extern "C" void kernel_launch(void* const* d_in, const int* in_sizes, int n_in,
                              void* d_out, int out_size) {
    const float* x  = (const float*)d_in[0];
    const float* Wf = (const float*)d_in[1];
    const float* bf = (const float*)d_in[2];
    const float* Wi = (const float*)d_in[3];
    const float* bi = (const float*)d_in[4];
    const float* Wc = (const float*)d_in[5];
    const float* bc = (const float*)d_in[6];
    const float* Wo = (const float*)d_in[7];
    const float* bo = (const float*)d_in[8];
    float* out = (float*)d_out;

    cudaFuncSetAttribute(xgemm_mma, cudaFuncAttributeMaxDynamicSharedMemorySize, P1_SMEM);
    dim3 g1(NG / 128, (B_ * S_) / 128);            // (32, 256)
    xgemm_mma<<<g1, 256, P1_SMEM>>>(x, Wf, Wi, Wc, Wo);

    cudaFuncSetAttribute(lstm_seq_mma, cudaFuncAttributeMaxDynamicSharedMemorySize, P2_SMEM);
    lstm_seq_mma<<<NCTA, 256, P2_SMEM>>>(Wf, bf, Wi, bi, Wc, bc, Wo, bo, out);
}

// round 8
// speedup vs baseline: 3.6294x; 1.6265x over previous
#include <cuda_runtime.h>
#include <cuda_fp16.h>
#include <cstdint>
#include <cstddef>

#define B_  64
#define S_  512
#define E_  1024
#define H_  1024
#define NG  4096
#define NCTA 128

// ---------------- device scratch ----------------
__device__ float  g_xg[(size_t)S_ * B_ * NG];     // [t][b][n] fp32
__device__ __half g_xh[(size_t)B_ * S_ * E_];     // x in fp16
__device__ __half g_wh[(size_t)NG * E_];          // Wx in fp16, [gate-major n][k]
__device__ __half g_hh[2][B_ * H_];               // hidden state fp16, [b][k]
__device__ unsigned g_bar_count = 0;
__device__ unsigned g_bar_gen   = 0;

// ---------------- helpers ----------------
__device__ __forceinline__ uint32_t smem_u32(const void* p) {
    uint32_t a;
    asm("{ .reg .u64 t; cvta.to.shared.u64 t, %1; cvt.u32.u64 %0, t; }" : "=r"(a) : "l"(p));
    return a;
}
__device__ __forceinline__ void cpa16(uint32_t saddr, const void* g) {
    asm volatile("cp.async.cg.shared.global [%0], [%1], 16;" :: "r"(saddr), "l"(g) : "memory");
}
__device__ __forceinline__ void cpa_commit() {
    asm volatile("cp.async.commit_group;" ::: "memory");
}
template<int N> __device__ __forceinline__ void cpa_wait() {
    asm volatile("cp.async.wait_group %0;" :: "n"(N) : "memory");
}
__device__ __forceinline__ void ldmx4(uint32_t* r, uint32_t addr) {
    asm volatile("ldmatrix.sync.aligned.m8n8.x4.shared.b16 {%0,%1,%2,%3}, [%4];"
        : "=r"(r[0]), "=r"(r[1]), "=r"(r[2]), "=r"(r[3]) : "r"(addr));
}
__device__ __forceinline__ void mma16(float* d, const uint32_t* a, const uint32_t* b) {
    asm("mma.sync.aligned.m16n8k16.row.col.f32.f16.f16.f32 "
        "{%0,%1,%2,%3}, {%4,%5,%6,%7}, {%8,%9}, {%0,%1,%2,%3};"
        : "+f"(d[0]), "+f"(d[1]), "+f"(d[2]), "+f"(d[3])
        : "r"(a[0]), "r"(a[1]), "r"(a[2]), "r"(a[3]), "r"(b[0]), "r"(b[1]));
}
__device__ __forceinline__ float sigm(float z) { return 1.f / (1.f + expf(-z)); }

__device__ __forceinline__ void grid_barrier() {
    __syncthreads();
    if (threadIdx.x == 0) {
        __threadfence();
        unsigned gen = *(volatile unsigned*)&g_bar_gen;
        if (atomicAdd(&g_bar_count, 1u) == NCTA - 1) {
            atomicExch(&g_bar_count, 0u);
            __threadfence();
            atomicAdd(&g_bar_gen, 1u);
        } else {
            while (*(volatile unsigned*)&g_bar_gen == gen) __nanosleep(32);
        }
        __threadfence();
    }
    __syncthreads();
}

// ===========================================================================
// Kernel 0: convert x and Wx (x-part columns) to fp16 scratch.
// ===========================================================================
__global__ void convert_h(
    const float* __restrict__ x,
    const float* __restrict__ Wf, const float* __restrict__ Wi,
    const float* __restrict__ Wc, const float* __restrict__ Wo)
{
    const int stride = gridDim.x * blockDim.x;
    const int i0 = blockIdx.x * blockDim.x + threadIdx.x;
    const int NX = B_ * S_ * E_ / 2;
    for (int i = i0; i < NX; i += stride) {
        float2 v = *(const float2*)(x + (size_t)2 * i);
        ((__half2*)g_xh)[i] = __floats2half2_rn(v.x, v.y);
    }
    const int NW = NG * E_ / 2;
    for (int i = i0; i < NW; i += stride) {
        int n = i >> 9, k2 = i & 511;
        const float* Ws = (n < 1024) ? Wf : (n < 2048) ? Wi : (n < 3072) ? Wc : Wo;
        float2 v = *(const float2*)(Ws + (size_t)(n & 1023) * 2048 + k2 * 2);
        ((__half2*)g_wh)[i] = __floats2half2_rn(v.x, v.y);
    }
}

// ===========================================================================
// Phase 1: Xg = x @ Wx^T (fp16 mma, ldmatrix, cp.async 3-stage).
// CTA tile 128x128, K chunks of 64. 8 warps = 2(M) x 4(N), warp tile 64x32.
// Stage: A[128][72] half + B[128][72] half = 36864 B; 3 stages.
// ===========================================================================
#define P1_STAGE 36864
#define P1_SMEM  (3 * P1_STAGE)

__device__ __forceinline__ void p1_issue(uint32_t sb, int m0, int n0, int k0, int tid) {
    const int r = tid >> 3, c = tid & 7;
#pragma unroll
    for (int j = 0; j < 4; j++) {
        int rr = r + j * 32;
        cpa16(sb + rr * 144 + c * 16,         g_xh + (size_t)(m0 + rr) * E_ + k0 + c * 8);
        cpa16(sb + 18432 + rr * 144 + c * 16, g_wh + (size_t)(n0 + rr) * E_ + k0 + c * 8);
    }
    cpa_commit();
}

__global__ void __launch_bounds__(256, 2) xgemm_h()
{
    extern __shared__ char sm[];
    const uint32_t smb = smem_u32(sm);

    const int tid = threadIdx.x;
    const int wid = tid >> 5, lane = tid & 31;
    const int gid = lane >> 2, tg = lane & 3;
    const int wm = wid >> 2, wn = wid & 3;
    const int m0 = blockIdx.y * 128;
    const int n0 = blockIdx.x * 128;

    // per-lane ldmatrix offsets
    uint32_t laneA[4], laneB[2];
#pragma unroll
    for (int mi = 0; mi < 4; mi++)
        laneA[mi] = (wm * 64 + mi * 16 + ((lane >> 3) & 1) * 8 + (lane & 7)) * 144
                  + (lane >> 4) * 16;
#pragma unroll
    for (int p = 0; p < 2; p++)
        laneB[p] = 18432
                 + (wn * 32 + p * 16 + (lane >> 4) * 8 + (lane & 7)) * 144
                 + ((lane >> 3) & 1) * 16;

    float acc[4][4][4];
#pragma unroll
    for (int i = 0; i < 4; i++)
#pragma unroll
        for (int j = 0; j < 4; j++)
#pragma unroll
            for (int k = 0; k < 4; k++) acc[i][j][k] = 0.f;

    p1_issue(smb, m0, n0, 0, tid);
    p1_issue(smb + P1_STAGE, m0, n0, 64, tid);

    int st = 0;
    for (int ch = 0; ch < 16; ch++) {
        if (ch < 15) cpa_wait<1>(); else cpa_wait<0>();
        __syncthreads();
        if (ch + 2 < 16) {
            int st2 = st + 2; if (st2 >= 3) st2 -= 3;
            p1_issue(smb + st2 * P1_STAGE, m0, n0, (ch + 2) * 64, tid);
        }
        const uint32_t sb = smb + st * P1_STAGE;
#pragma unroll
        for (int kk = 0; kk < 4; kk++) {
            uint32_t a[4][4], b[2][4];
#pragma unroll
            for (int mi = 0; mi < 4; mi++) ldmx4(a[mi], sb + laneA[mi] + kk * 32);
#pragma unroll
            for (int p = 0; p < 2; p++)   ldmx4(b[p],  sb + laneB[p] + kk * 32);
#pragma unroll
            for (int mi = 0; mi < 4; mi++)
#pragma unroll
                for (int ni = 0; ni < 4; ni++)
                    mma16(acc[mi][ni], a[mi], b[ni >> 1] + (ni & 1) * 2);
        }
        if (++st >= 3) st -= 3;
    }

    // epilogue: frags -> g_xg[t][b][n]
#pragma unroll
    for (int mi = 0; mi < 4; mi++) {
        int row = m0 + wm * 64 + mi * 16 + gid;
        int b = row >> 9, t = row & (S_ - 1);
#pragma unroll
        for (int ni = 0; ni < 4; ni++) {
            int col = n0 + wn * 32 + ni * 8 + tg * 2;
            float* p0 = g_xg + ((size_t)t * B_ + b) * NG + col;
            float* p1 = g_xg + ((size_t)(t + 8) * B_ + b) * NG + col;
            *(float2*)p0 = make_float2(acc[mi][ni][0], acc[mi][ni][1]);
            *(float2*)p1 = make_float2(acc[mi][ni][2], acc[mi][ni][3]);
        }
    }
}

// ===========================================================================
// Phase 2: persistent scan, fp16 mma, full h staged per step, no split-K.
// CTA owns 32 gate-cols. Wh fp16 [32][1032] resident; h buf [64][1032].
// 8 warps = 4(mi) x 2(ni-pair); full-K register accumulators.
// ===========================================================================
#define HROW   2064                       // bytes per SMEM row (1032 halves)
#define WH_OFF 0                          // 32*2064  = 66048
#define AB_OFF 66048                      // 64*2064  = 132096
#define ZB_OFF 198144                     // 64*34*4  = 8704
#define CS_OFF 206848                     // 2048
#define BS_OFF 208896                     // 128
#define P2_SMEM 209024

template<int W>
__device__ __forceinline__ void p2_group(int ksb, uint32_t aA, uint32_t aB, float acc[2][4]) {
    cpa_wait<W>();
    __syncthreads();
#pragma unroll
    for (int ks = 0; ks < 16; ks++) {
        uint32_t a[4], b[4];
        ldmx4(a, aA + (ksb + ks) * 32);
        ldmx4(b, aB + (ksb + ks) * 32);
        mma16(acc[0], a, b);
        mma16(acc[1], a, b + 2);
    }
}

__global__ void __launch_bounds__(256, 1) lstm_seq_h(
    const float* __restrict__ Wf, const float* __restrict__ bf,
    const float* __restrict__ Wi, const float* __restrict__ bi,
    const float* __restrict__ Wc, const float* __restrict__ bc,
    const float* __restrict__ Wo, const float* __restrict__ bo,
    float* __restrict__ out)
{
    extern __shared__ char sm[];
    float* zbf = (float*)(sm + ZB_OFF);
    float* csm = (float*)(sm + CS_OFF);
    float* bsm = (float*)(sm + BS_OFF);

    const int tid = threadIdx.x;
    const int wid = tid >> 5, lane = tid & 31;
    const int gid = lane >> 2, tg = lane & 3;
    const int mi = wid >> 1, nh = wid & 1;
    const int cta = blockIdx.x;
    const float* Wp[4] = {Wf, Wi, Wc, Wo};
    const float* bp[4] = {bf, bi, bc, bo};

    // one-time: Wh slice -> SMEM fp16 [32 n][1024 k] (padded rows)
    for (int idx = tid; idx < 32 * 512; idx += 256) {
        int n = idx >> 9, k2 = idx & 511;
        float2 v = *(const float2*)(Wp[n >> 3] + (size_t)(cta * 8 + (n & 7)) * 2048 + 1024 + k2 * 2);
        *(__half2*)(sm + WH_OFF + n * HROW + k2 * 4) = __floats2half2_rn(v.x, v.y);
    }
    if (tid < 32) bsm[tid] = bp[tid >> 3][cta * 8 + (tid & 7)];
    for (int i = tid; i < 512; i += 256) {
        csm[i] = 0.f;
        g_hh[0][(i >> 3) * H_ + cta * 8 + (i & 7)] = __float2half(0.f);
    }
    __syncthreads();
    grid_barrier();

    const uint32_t abBase = smem_u32(sm + AB_OFF);
    const uint32_t aA = abBase
        + (mi * 16 + ((lane >> 3) & 1) * 8 + (lane & 7)) * HROW + (lane >> 4) * 16;
    const uint32_t aB = smem_u32(sm + WH_OFF)
        + (nh * 16 + (lane >> 4) * 8 + (lane & 7)) * HROW + ((lane >> 3) & 1) * 16;

    for (int t = 0; t < S_; t++) {
        const __half* hcur = g_hh[t & 1];
        // stage full h (128 KB) in 4 cp.async commit groups (k quarters)
#pragma unroll
        for (int g = 0; g < 4; g++) {
#pragma unroll
            for (int j = 0; j < 8; j++) {
                int idx = tid + j * 256;
                int r = idx >> 5, c = idx & 31;
                cpa16(abBase + r * HROW + g * 512 + c * 16,
                      hcur + r * H_ + g * 256 + c * 8);
            }
            cpa_commit();
        }

        float acc[2][4];
#pragma unroll
        for (int p = 0; p < 2; p++)
#pragma unroll
            for (int k = 0; k < 4; k++) acc[p][k] = 0.f;

        p2_group<3>(0,  aA, aB, acc);
        p2_group<2>(16, aA, aB, acc);
        p2_group<1>(32, aA, aB, acc);
        p2_group<0>(48, aA, aB, acc);

        // write z to SMEM
        const int row0 = mi * 16 + gid;
#pragma unroll
        for (int p = 0; p < 2; p++) {
            int col = (nh * 2 + p) * 8 + tg * 2;
            *(float2*)&zbf[row0 * 34 + col]       = make_float2(acc[p][0], acc[p][1]);
            *(float2*)&zbf[(row0 + 8) * 34 + col] = make_float2(acc[p][2], acc[p][3]);
        }
        __syncthreads();

        // gate math; c stays in SMEM; h -> fp16 global + fp32 output
        __half* hnext = g_hh[(t + 1) & 1];
        for (int i = tid; i < 512; i += 256) {
            int b = i >> 3, r = i & 7;
            const float* xgb = g_xg + ((size_t)t * B_ + b) * NG + cta * 8 + r;
            float zf = zbf[b * 34 + r]      + bsm[r]      + __ldg(xgb);
            float zi = zbf[b * 34 + 8 + r]  + bsm[8 + r]  + __ldg(xgb + 1024);
            float zg = zbf[b * 34 + 16 + r] + bsm[16 + r] + __ldg(xgb + 2048);
            float zo = zbf[b * 34 + 24 + r] + bsm[24 + r] + __ldg(xgb + 3072);
            float cc = sigm(zf) * csm[i] + sigm(zi) * tanhf(zg);
            csm[i] = cc;
            float h = sigm(zo) * tanhf(cc);
            int hc = cta * 8 + r;
            hnext[b * H_ + hc] = __float2half(h);
            out[((size_t)b * S_ + t) * H_ + hc] = h;
            if (t == S_ - 1) {
                out[(size_t)B_ * S_ * H_ + b * H_ + hc] = h;                    // hT
                out[(size_t)B_ * S_ * H_ + (size_t)B_ * H_ + b * H_ + hc] = cc; // cT
            }
        }
        grid_barrier();
    }
}

// ===========================================================================
extern "C" void kernel_launch(void* const* d_in, const int* in_sizes, int n_in,
                              void* d_out, int out_size) {
    const float* x  = (const float*)d_in[0];
    const float* Wf = (const float*)d_in[1];
    const float* bf = (const float*)d_in[2];
    const float* Wi = (const float*)d_in[3];
    const float* bi = (const float*)d_in[4];
    const float* Wc = (const float*)d_in[5];
    const float* bc = (const float*)d_in[6];
    const float* Wo = (const float*)d_in[7];
    const float* bo = (const float*)d_in[8];
    float* out = (float*)d_out;

    convert_h<<<1024, 256>>>(x, Wf, Wi, Wc, Wo);

    cudaFuncSetAttribute(xgemm_h, cudaFuncAttributeMaxDynamicSharedMemorySize, P1_SMEM);
    dim3 g1(NG / 128, (B_ * S_) / 128);            // (32, 256)
    xgemm_h<<<g1, 256, P1_SMEM>>>();

    cudaFuncSetAttribute(lstm_seq_h, cudaFuncAttributeMaxDynamicSharedMemorySize, P2_SMEM);
    lstm_seq_h<<<NCTA, 256, P2_SMEM>>>(Wf, bf, Wi, bi, Wc, bc, Wo, bo, out);
}